// round 13
// baseline (speedup 1.0000x reference)
#include <cuda_runtime.h>
#include <cuda_bf16.h>
#include <cstdint>
#include <cstddef>

#define CN 22
#define FN 192
#define HN 128
#define TM 88                   // CTA M-tile = 4 bt-groups
#define G  4
#define NTH 384                 // 12 warps: 6 M x 2 N, warp tile 16x64

// weights pre-split bf16 hi/lo, MMA-fragment order: t = s*512 + f*32 + lane
__device__ uint4 g_W0s[(FN / 16) * 512];
__device__ uint4 g_W1s[(HN / 16) * 512];

// ---- smem layout (bytes) ----
// Region R [0, 50688): phase1 = two X buffers (uint2[96][20] = 15360 each),
//                      phase2/4 = U/V tile float[96][132] = 50688
#define XSTRIDE 20              // uint2 per row
#define XBUF    15360
#define USTRIDE 132
// H: uint2[96][68] interleaved {hi,lo}
#define OFF_H   50688
#define HSTRIDE 68
#define OFF_A   102912          // float[4][22][24] = 8448
#define SMEM_TOTAL 111360

__device__ __forceinline__ uint32_t pack_bf16(float x, float y) {
    __nv_bfloat162 p;
    p.x = __float2bfloat16(x);
    p.y = __float2bfloat16(y);
    return *reinterpret_cast<uint32_t*>(&p);
}
__device__ __forceinline__ uint32_t pack_bf16_resid(float x, float y, uint32_t hi) {
    __nv_bfloat162 h = *reinterpret_cast<__nv_bfloat162*>(&hi);
    return pack_bf16(x - __bfloat162float(h.x), y - __bfloat162float(h.y));
}

// ---- weight prep: W [128][K] fp32 -> fragment-order split bf16 ----
__global__ void prep_w(const float* __restrict__ W, int K, uint4* __restrict__ out) {
    int t = blockIdx.x * blockDim.x + threadIdx.x;
    int total = (K / 16) * 512;
    if (t >= total) return;
    int l = t & 31;
    int f = (t >> 5) & 15;
    int s = t >> 9;
    int n = f * 8 + (l >> 2);
    int k0 = s * 16 + (l & 3) * 2;
    const float* wr = W + (size_t)n * K;
    float w00 = wr[k0], w01 = wr[k0 + 1], w10 = wr[k0 + 8], w11 = wr[k0 + 9];
    uint32_t h0 = pack_bf16(w00, w01), h1 = pack_bf16(w10, w11);
    uint32_t l0 = pack_bf16_resid(w00, w01, h0), l1 = pack_bf16_resid(w10, w11, h1);
    out[t] = make_uint4(h0, h1, l0, l1);
}

// ---- mma.sync m16n8k16 row.col bf16 -> f32 ----
__device__ __forceinline__ void mma_bf16(float* c, const uint32_t* a, uint32_t b0, uint32_t b1) {
    asm volatile(
        "mma.sync.aligned.m16n8k16.row.col.f32.bf16.bf16.f32 "
        "{%0,%1,%2,%3}, {%4,%5,%6,%7}, {%8,%9}, {%0,%1,%2,%3};"
        : "+f"(c[0]), "+f"(c[1]), "+f"(c[2]), "+f"(c[3])
        : "r"(a[0]), "r"(a[1]), "r"(a[2]), "r"(a[3]), "r"(b0), "r"(b1));
}

// stage 8 fp32 (one thread's k-quarter) as interleaved {hi,lo} uint2 pairs
__device__ __forceinline__ void stage_x(char* buf, int sr, int sq, float4 a, float4 b) {
    uint32_t h0 = pack_bf16(a.x, a.y), h1 = pack_bf16(a.z, a.w);
    uint32_t h2 = pack_bf16(b.x, b.y), h3 = pack_bf16(b.z, b.w);
    uint32_t l0 = pack_bf16_resid(a.x, a.y, h0), l1 = pack_bf16_resid(a.z, a.w, h1);
    uint32_t l2 = pack_bf16_resid(b.x, b.y, h2), l3 = pack_bf16_resid(b.z, b.w, h3);
    uint4* dst = reinterpret_cast<uint4*>(buf + (size_t)sr * (XSTRIDE * 8) + sq * 32);
    dst[0] = make_uint4(h0, l0, h1, l1);
    dst[1] = make_uint4(h2, l2, h3, l3);
}

// ---- whole network, one kernel, 2 CTAs/SM ----
__global__ void __launch_bounds__(NTH, 2) fused_all(
    const float* __restrict__ x,
    const uint4* __restrict__ W0s, const uint4* __restrict__ W1s,
    const float* __restrict__ A,
    const float* __restrict__ b0, const float* __restrict__ b1,
    float* __restrict__ out)
{
    extern __shared__ __align__(16) char sm[];
    const int t = threadIdx.x;
    const int wid = t >> 5, l = t & 31;
    const int g = l >> 2, q = l & 3;
    const int wm = wid >> 1, wn = wid & 1;
    const int rb = wm * 16;
    const int row0 = blockIdx.x * TM;
    const int bt0 = blockIdx.x * G;

    float* sU = reinterpret_cast<float*>(sm);
    uint2* sH = reinterpret_cast<uint2*>(sm + OFF_H);
    float* sA = reinterpret_cast<float*>(sm + OFF_A);

    // ---- load A (persistent) ----
    {
        const float* Ag = A + (size_t)bt0 * (CN * CN);
        for (int i = t; i < G * CN * CN; i += NTH) {
            int gg = i / (CN * CN);
            int rem = i - gg * (CN * CN);
            int c = rem / CN;
            int j = rem - c * CN;
            sA[gg * 528 + c * 24 + j] = Ag[i];
        }
    }

    float acc[8][4];
#pragma unroll
    for (int f = 0; f < 8; f++)
#pragma unroll
        for (int i = 0; i < 4; i++) acc[f][i] = 0.f;

    // ---- phase 1: U = x @ W0^T (K=192), X double-buffered, W via LDG ----
    const int sr = t >> 2, sq = t & 3;
    const bool stager = (t < TM * 4);
    const float* xrow = x + (size_t)(row0 + sr) * FN + sq * 8;

    if (stager) {
        float4 a0 = *reinterpret_cast<const float4*>(xrow);
        float4 a1 = *reinterpret_cast<const float4*>(xrow + 4);
        stage_x(sm, sr, sq, a0, a1);
    }
    __syncthreads();

    constexpr int NC1 = FN / 32;   // 6
#pragma unroll 1
    for (int kc = 0; kc < NC1; kc++) {
        char* bufc = sm + (kc & 1) * XBUF;
        char* bufn = sm + ((kc & 1) ^ 1) * XBUF;
        float4 xv0, xv1;
        const bool pf = stager && (kc + 1 < NC1);
        if (pf) {
            xv0 = *reinterpret_cast<const float4*>(xrow + (kc + 1) * 32);
            xv1 = *reinterpret_cast<const float4*>(xrow + (kc + 1) * 32 + 4);
        }

        const uint2* sX = reinterpret_cast<const uint2*>(bufc);
#pragma unroll
        for (int sp = 0; sp < 2; sp++) {
            int p0 = sp * 8 + q;
            uint2 u00 = sX[(rb + g) * XSTRIDE + p0];
            uint2 u10 = sX[(rb + 8 + g) * XSTRIDE + p0];
            uint2 u01 = sX[(rb + g) * XSTRIDE + p0 + 4];
            uint2 u11 = sX[(rb + 8 + g) * XSTRIDE + p0 + 4];
            uint32_t ah[4] = { u00.x, u10.x, u01.x, u11.x };
            uint32_t al[4] = { u00.y, u10.y, u01.y, u11.y };
            const uint4* Wp = W0s + (size_t)(kc * 2 + sp) * 512 + wn * 256 + l;
#pragma unroll
            for (int f = 0; f < 8; f++) {
                uint4 bv = __ldg(Wp + f * 32);
                mma_bf16(acc[f], ah, bv.x, bv.y);
                mma_bf16(acc[f], al, bv.x, bv.y);
                mma_bf16(acc[f], ah, bv.z, bv.w);
            }
        }
        if (pf) stage_x(bufn, sr, sq, xv0, xv1);
        __syncthreads();
    }

    // ---- phase 2: acc -> sU; mix1 -> H split (interleaved uint2) ----
    {
        int rg = rb + g;
#pragma unroll
        for (int f = 0; f < 8; f++) {
            int cb = wn * 64 + f * 8 + 2 * q;
            *reinterpret_cast<float2*>(&sU[rg * USTRIDE + cb]) =
                make_float2(acc[f][0], acc[f][1]);
            *reinterpret_cast<float2*>(&sU[(rg + 8) * USTRIDE + cb]) =
                make_float2(acc[f][2], acc[f][3]);
        }
    }
    __syncthreads();

    if (t < G * 64) {        // unit = (group gg, h-pair p)
        int gg = t >> 6, p = t & 63;
        float2 bp = *reinterpret_cast<const float2*>(b0 + 2 * p);
        float2 uu[CN];
#pragma unroll
        for (int j = 0; j < CN; j++)
            uu[j] = *reinterpret_cast<const float2*>(&sU[(gg * CN + j) * USTRIDE + 2 * p]);
#pragma unroll
        for (int c = 0; c < CN; c++) {
            const float* ar = &sA[gg * 528 + c * 24];
            float s0 = 0.f, s1 = 0.f;
#pragma unroll
            for (int jq = 0; jq < 5; jq++) {
                float4 a4 = *reinterpret_cast<const float4*>(ar + jq * 4);
                s0 = fmaf(a4.x, uu[jq * 4 + 0].x, s0); s1 = fmaf(a4.x, uu[jq * 4 + 0].y, s1);
                s0 = fmaf(a4.y, uu[jq * 4 + 1].x, s0); s1 = fmaf(a4.y, uu[jq * 4 + 1].y, s1);
                s0 = fmaf(a4.z, uu[jq * 4 + 2].x, s0); s1 = fmaf(a4.z, uu[jq * 4 + 2].y, s1);
                s0 = fmaf(a4.w, uu[jq * 4 + 3].x, s0); s1 = fmaf(a4.w, uu[jq * 4 + 3].y, s1);
            }
            float2 a2 = *reinterpret_cast<const float2*>(ar + 20);
            s0 = fmaf(a2.x, uu[20].x, s0); s1 = fmaf(a2.x, uu[20].y, s1);
            s0 = fmaf(a2.y, uu[21].x, s0); s1 = fmaf(a2.y, uu[21].y, s1);
            float v0 = fmaxf(s0 + bp.x, 0.f);
            float v1 = fmaxf(s1 + bp.y, 0.f);
            uint32_t hi = pack_bf16(v0, v1);
            uint32_t lo = pack_bf16_resid(v0, v1, hi);
            sH[(gg * CN + c) * HSTRIDE + p] = make_uint2(hi, lo);
        }
    }
    __syncthreads();

    // ---- phase 3: V = H @ W1^T (K=128); a-frags LDS.64 from sH, W via LDG; no syncs ----
#pragma unroll
    for (int f = 0; f < 8; f++)
#pragma unroll
        for (int i = 0; i < 4; i++) acc[f][i] = 0.f;

    constexpr int NC2 = HN / 32;   // 4
#pragma unroll 1
    for (int kc = 0; kc < NC2; kc++) {
#pragma unroll
        for (int sp = 0; sp < 2; sp++) {
            int p0 = kc * 16 + sp * 8 + q;
            uint2 u00 = sH[(rb + g) * HSTRIDE + p0];
            uint2 u10 = sH[(rb + 8 + g) * HSTRIDE + p0];
            uint2 u01 = sH[(rb + g) * HSTRIDE + p0 + 4];
            uint2 u11 = sH[(rb + 8 + g) * HSTRIDE + p0 + 4];
            uint32_t ah[4] = { u00.x, u10.x, u01.x, u11.x };
            uint32_t al[4] = { u00.y, u10.y, u01.y, u11.y };
            const uint4* Wp = W1s + (size_t)(kc * 2 + sp) * 512 + wn * 256 + l;
#pragma unroll
            for (int f = 0; f < 8; f++) {
                uint4 bv = __ldg(Wp + f * 32);
                mma_bf16(acc[f], ah, bv.x, bv.y);
                mma_bf16(acc[f], al, bv.x, bv.y);
                mma_bf16(acc[f], ah, bv.z, bv.w);
            }
        }
    }

    // ---- phase 4: acc -> sU (disjoint from sH: no barrier needed before stores) ----
    {
        int rg = rb + g;
#pragma unroll
        for (int f = 0; f < 8; f++) {
            int cb = wn * 64 + f * 8 + 2 * q;
            *reinterpret_cast<float2*>(&sU[rg * USTRIDE + cb]) =
                make_float2(acc[f][0], acc[f][1]);
            *reinterpret_cast<float2*>(&sU[(rg + 8) * USTRIDE + cb]) =
                make_float2(acc[f][2], acc[f][3]);
        }
    }
    __syncthreads();

    // ---- mix2 + mean -> out ----
    for (int u = t; u < G * HN; u += NTH) {
        int gg = u >> 7, h = u & 127;
        float uu[CN];
#pragma unroll
        for (int j = 0; j < CN; j++) uu[j] = sU[(gg * CN + j) * USTRIDE + h];
        float bh = __ldg(b1 + h);
        float tot = 0.f;
#pragma unroll
        for (int c = 0; c < CN; c++) {
            const float* ar = &sA[gg * 528 + c * 24];
            float s = 0.f;
#pragma unroll
            for (int jq = 0; jq < 5; jq++) {
                float4 a4 = *reinterpret_cast<const float4*>(ar + jq * 4);
                s = fmaf(a4.x, uu[jq * 4 + 0], s);
                s = fmaf(a4.y, uu[jq * 4 + 1], s);
                s = fmaf(a4.z, uu[jq * 4 + 2], s);
                s = fmaf(a4.w, uu[jq * 4 + 3], s);
            }
            float2 a2 = *reinterpret_cast<const float2*>(ar + 20);
            s = fmaf(a2.x, uu[20], s);
            s = fmaf(a2.y, uu[21], s);
            tot += fmaxf(s + bh, 0.f);
        }
        out[(size_t)(bt0 + gg) * HN + h] = tot * (1.0f / 22.0f);
    }
}

// ---------------- launch ----------------
extern "C" void kernel_launch(void* const* d_in, const int* in_sizes, int n_in,
                              void* d_out, int out_size) {
    const float* x  = (const float*)d_in[0];
    const float* A  = (const float*)d_in[1];
    const float* W0 = (const float*)d_in[2];
    const float* b0 = (const float*)d_in[3];
    const float* W1 = (const float*)d_in[4];
    const float* b1 = (const float*)d_in[5];
    float* out = (float*)d_out;

    const int BT = in_sizes[1] / (CN * CN);      // 16384
    const int grid = (BT * CN) / TM;             // 4096

    void *pW0 = nullptr, *pW1 = nullptr;
    cudaGetSymbolAddress(&pW0, g_W0s);
    cudaGetSymbolAddress(&pW1, g_W1s);
    uint4* W0s = (uint4*)pW0;
    uint4* W1s = (uint4*)pW1;

    cudaFuncSetAttribute(fused_all,
                         cudaFuncAttributeMaxDynamicSharedMemorySize, SMEM_TOTAL);

    const int n0 = (FN / 16) * 512;              // 6144
    const int n1 = (HN / 16) * 512;              // 4096
    prep_w<<<(n0 + 255) / 256, 256>>>(W0, FN, W0s);
    prep_w<<<(n1 + 255) / 256, 256>>>(W1, HN, W1s);

    fused_all<<<grid, NTH, SMEM_TOTAL>>>(x, W0s, W1s, A, b0, b1, out);
}